// round 1
// baseline (speedup 1.0000x reference)
#include <cuda_runtime.h>

#define THREADS 256
#define NTILES  65   // ceil(4102 / 64)

// db4 decomposition filters, reversed (out[i] = sum_k x[2i-6+k] * filt[7-k])
static __device__ __constant__ float c_rlo[8] = {
     0.23037781330885523f,  0.7148465705525415f,   0.6308807679295904f,  -0.02798376941698385f,
    -0.18703481171888114f,  0.030841381835986965f, 0.032883011666982945f, -0.010597401784997278f};
static __device__ __constant__ float c_rhi[8] = {
    -0.010597401784997278f, -0.032883011666982945f, 0.030841381835986965f, 0.18703481171888114f,
    -0.02798376941698385f,  -0.6308807679295904f,   0.7148465705525415f,  -0.23037781330885523f};

__global__ __launch_bounds__(THREADS)
void dwt6_kernel(const float* __restrict__ x, float* __restrict__ out)
{
    // M[l] = length of cA_l per row (l=0 is the input)
    constexpr int M[7] = {262144, 131075, 65541, 32774, 16390, 8198, 4102};
    // Output element offsets of each detail tensor (cA6 at 0):
    // order: cA6, cD6, cD5, cD4, cD3, cD2, cD1
    constexpr long long DOFF[7] = {0, 8390848LL, 4196224LL, 2098688LL,
                                   1049728LL, 525056LL, 262528LL};

    // Max halo-extended widths: w0=4474, w1=2234 (+16 margins)
    __shared__ __align__(16) float buf0[4512];
    __shared__ __align__(16) float buf1[2272];

    const int tile = blockIdx.x;   // 0..64
    const int row  = blockIdx.y;   // 0..63
    const int tid  = threadIdx.x;

    // Needed cA ranges per level: lo always even by construction.
    int lo[7], hi[7];
    lo[6] = tile << 6;
    hi[6] = min(lo[6] + 64, M[6]);
#pragma unroll
    for (int l = 5; l >= 0; --l) {
        lo[l] = max(2 * lo[l + 1] - 6, 0);
        hi[l] = min(2 * hi[l + 1], M[l]);
    }

    float rlo[8], rhi[8];
#pragma unroll
    for (int k = 0; k < 8; ++k) { rlo[k] = c_rlo[k]; rhi[k] = c_rhi[k]; }

    // Stage level-0 input slice into buf0 (float2: lo[0] even, width even).
    {
        const int w0 = hi[0] - lo[0];
        const float2* xr = reinterpret_cast<const float2*>(x + (size_t)row * 262144 + lo[0]);
        float2* b2 = reinterpret_cast<float2*>(buf0) + 4;   // data at float index 8
        for (int t = tid; t < (w0 >> 1); t += THREADS) b2[t] = xr[t];
        if (tid < 16) buf0[tid < 8 ? tid : w0 + tid] = 0.0f;  // zero margins
    }
    __syncthreads();

    float* src = buf0;
    float* dst = buf1;
#pragma unroll
    for (int l = 1; l <= 6; ++l) {
        const int llo   = lo[l], lhi = hi[l];
        const int wl    = lhi - llo;
        const int shalf = lo[l - 1] >> 1;
        const int al    = tile << (12 - l);                      // owned detail range
        const int bl    = min(al + (1 << (12 - l)), M[l]);

        if (l < 6 && tid < 16) dst[tid < 8 ? tid : wl + tid] = 0.0f;

        const float2* s2  = reinterpret_cast<const float2*>(src);
        float* dA   = dst + 8 - llo;
        float* outA = out + (size_t)row * M[6];
        float* outD = out + DOFF[l] + (size_t)row * M[l];

        for (int i = llo + tid; i < lhi; i += THREADS) {
            // window x[2i-6 .. 2i+1] -> 4 aligned float2 smem loads
            const int p = i + 1 - shalf;
            const float2 q0 = s2[p], q1 = s2[p + 1], q2 = s2[p + 2], q3 = s2[p + 3];
            const float w[8] = {q0.x, q0.y, q1.x, q1.y, q2.x, q2.y, q3.x, q3.y};
            float aA = 0.0f, aD = 0.0f;
#pragma unroll
            for (int k = 0; k < 8; ++k) {
                aA = fmaf(w[k], rlo[k], aA);
                aD = fmaf(w[k], rhi[k], aD);
            }
            if (l < 6) dA[i] = aA;          // cA to smem for next level
            else       outA[i] = aA;        // cA6 to gmem
            if (i >= al && i < bl) outD[i] = aD;   // owned cD to gmem
        }
        __syncthreads();
        float* t = src; src = dst; dst = t;
    }
}

extern "C" void kernel_launch(void* const* d_in, const int* in_sizes, int n_in,
                              void* d_out, int out_size)
{
    (void)in_sizes; (void)n_in; (void)out_size;
    dim3 grid(NTILES, 64);
    dwt6_kernel<<<grid, THREADS>>>((const float*)d_in[0], (float*)d_out);
}

// round 6
// speedup vs baseline: 1.0593x; 1.0593x over previous
#include <cuda_runtime.h>

#define THREADS 256
#define NTILES  65   // ceil(4102 / 64)

// db4 reversed decomposition filters as literal immediates (FFMA-imm, rt=1)
#define RL0 ( 0.23037781330885523f)
#define RL1 ( 0.7148465705525415f)
#define RL2 ( 0.6308807679295904f)
#define RL3 (-0.02798376941698385f)
#define RL4 (-0.18703481171888114f)
#define RL5 ( 0.030841381835986965f)
#define RL6 ( 0.032883011666982945f)
#define RL7 (-0.010597401784997278f)
#define RH0 (-0.010597401784997278f)
#define RH1 (-0.032883011666982945f)
#define RH2 ( 0.030841381835986965f)
#define RH3 ( 0.18703481171888114f)
#define RH4 (-0.02798376941698385f)
#define RH5 (-0.6308807679295904f)
#define RH6 ( 0.7148465705525415f)
#define RH7 (-0.23037781330885523f)

// 8-tap A/D dot product on window starting at float2* s (floats 2p..2p+7)
#define TAPS(s, A, D) do {                                              \
    const float2 q0 = (s)[0], q1 = (s)[1], q2 = (s)[2], q3 = (s)[3];    \
    A = q0.x * RL0;            D = q0.x * RH0;                          \
    A = fmaf(q0.y, RL1, A);    D = fmaf(q0.y, RH1, D);                  \
    A = fmaf(q1.x, RL2, A);    D = fmaf(q1.x, RH2, D);                  \
    A = fmaf(q1.y, RL3, A);    D = fmaf(q1.y, RH3, D);                  \
    A = fmaf(q2.x, RL4, A);    D = fmaf(q2.x, RH4, D);                  \
    A = fmaf(q2.y, RL5, A);    D = fmaf(q2.y, RH5, D);                  \
    A = fmaf(q3.x, RL6, A);    D = fmaf(q3.x, RH6, D);                  \
    A = fmaf(q3.y, RL7, A);    D = fmaf(q3.y, RH7, D);                  \
} while (0)

__global__ __launch_bounds__(THREADS)
void dwt6_kernel(const float* __restrict__ x, float* __restrict__ out)
{
    // M[l] = length of cA_l per row (l=0 is the input)
    constexpr int M[7] = {262144, 131075, 65541, 32774, 16390, 8198, 4102};
    // Output element offsets: order cA6, cD6, cD5, cD4, cD3, cD2, cD1
    constexpr long long DOFF[7] = {0, 8390848LL, 4196224LL, 2098688LL,
                                   1049728LL, 525056LL, 262528LL};

    __shared__ __align__(16) float buf0[4512];   // 8 + 4474 + 8 margin
    __shared__ __align__(16) float buf1[2272];   // 8 + 2234 + 8 margin

    const int tile = blockIdx.x;   // 0..64
    const int row  = blockIdx.y;   // 0..63
    const int tid  = threadIdx.x;

    int lo[7], hi[7];
    lo[6] = tile << 6;
    hi[6] = min(lo[6] + 64, M[6]);
#pragma unroll
    for (int l = 5; l >= 0; --l) {
        lo[l] = max(2 * lo[l + 1] - 6, 0);
        hi[l] = min(2 * hi[l + 1], M[l]);
    }

    // Stage level-0 input slice into buf0 (lo[0] even, width even).
    {
        const int w0 = hi[0] - lo[0];
        const float2* xr = reinterpret_cast<const float2*>(x + (size_t)row * 262144 + lo[0]);
        float2* b2 = reinterpret_cast<float2*>(buf0) + 4;   // data at float index 8
        for (int t = tid; t < (w0 >> 1); t += THREADS) b2[t] = xr[t];
        if (tid < 16) buf0[tid < 8 ? tid : w0 + tid] = 0.0f;  // zero margins
    }
    __syncthreads();

    float* src = buf0;
    float* dst = buf1;
#pragma unroll
    for (int l = 1; l <= 6; ++l) {
        const int llo   = lo[l], lhi = hi[l];
        const int wl    = lhi - llo;
        const int shalf = lo[l - 1] >> 1;
        const int al    = tile << (12 - l);   // owned-D lower bound (al - llo <= 186)

        if (l < 6 && tid < 16) dst[tid < 8 ? tid : wl + tid] = 0.0f;

        // window for output i lives at float2 index (i + 1 - shalf)
        const float2* sp = reinterpret_cast<const float2*>(src) + (llo + tid + 1 - shalf);
        float* outD = out + DOFF[l] + (size_t)row * M[l];

        if (l < 6) {
            float* dA = dst + 8 - llo;
            for (int i0 = llo + tid; i0 < lhi; i0 += 2 * THREADS, sp += 2 * THREADS) {
                float A0, D0;
                TAPS(sp, A0, D0);
                dA[i0] = A0;
                if (i0 >= al) outD[i0] = D0;
                const int i1 = i0 + THREADS;
                if (i1 < lhi) {                 // second output: always owned (halo < 256)
                    float A1, D1;
                    TAPS(sp + THREADS, A1, D1);
                    dA[i1] = A1;
                    outD[i1] = D1;
                }
            }
        } else {
            float* outA = out + (size_t)row * M[6];
            for (int i0 = llo + tid; i0 < lhi; i0 += THREADS, sp += THREADS) {
                float A0, D0;
                TAPS(sp, A0, D0);
                outA[i0] = A0;                  // lo[6] == al: every output owned
                outD[i0] = D0;
            }
        }
        __syncthreads();
        float* t = src; src = dst; dst = t;
    }
}

extern "C" void kernel_launch(void* const* d_in, const int* in_sizes, int n_in,
                              void* d_out, int out_size)
{
    (void)in_sizes; (void)n_in; (void)out_size;
    dim3 grid(NTILES, 64);
    dwt6_kernel<<<grid, THREADS>>>((const float*)d_in[0], (float*)d_out);
}

// round 7
// speedup vs baseline: 1.0685x; 1.0087x over previous
#include <cuda_runtime.h>

#define THREADS 256
#define NTILES  65   // ceil(4102 / 64)

// db4 reversed decomposition filters as literal immediates (FFMA-imm, rt=1)
#define RL0 ( 0.23037781330885523f)
#define RL1 ( 0.7148465705525415f)
#define RL2 ( 0.6308807679295904f)
#define RL3 (-0.02798376941698385f)
#define RL4 (-0.18703481171888114f)
#define RL5 ( 0.030841381835986965f)
#define RL6 ( 0.032883011666982945f)
#define RL7 (-0.010597401784997278f)
#define RH0 (-0.010597401784997278f)
#define RH1 (-0.032883011666982945f)
#define RH2 ( 0.030841381835986965f)
#define RH3 ( 0.18703481171888114f)
#define RH4 (-0.02798376941698385f)
#define RH5 (-0.6308807679295904f)
#define RH6 ( 0.7148465705525415f)
#define RH7 (-0.23037781330885523f)

// 8-tap A/D dot product on window starting at float2* s (floats 2p..2p+7)
#define TAPS(s, A, D) do {                                              \
    const float2 q0 = (s)[0], q1 = (s)[1], q2 = (s)[2], q3 = (s)[3];    \
    A = q0.x * RL0;            D = q0.x * RH0;                          \
    A = fmaf(q0.y, RL1, A);    D = fmaf(q0.y, RH1, D);                  \
    A = fmaf(q1.x, RL2, A);    D = fmaf(q1.x, RH2, D);                  \
    A = fmaf(q1.y, RL3, A);    D = fmaf(q1.y, RH3, D);                  \
    A = fmaf(q2.x, RL4, A);    D = fmaf(q2.x, RH4, D);                  \
    A = fmaf(q2.y, RL5, A);    D = fmaf(q2.y, RH5, D);                  \
    A = fmaf(q3.x, RL6, A);    D = fmaf(q3.x, RH6, D);                  \
    A = fmaf(q3.y, RL7, A);    D = fmaf(q3.y, RH7, D);                  \
} while (0)

__global__ __launch_bounds__(THREADS)
void dwt6_kernel(const float* __restrict__ x, float* __restrict__ out)
{
    // M[l] = length of cA_l per row (l=0 is the input)
    constexpr int M[7] = {262144, 131075, 65541, 32774, 16390, 8198, 4102};
    // Output element offsets: order cA6, cD6, cD5, cD4, cD3, cD2, cD1
    constexpr long long DOFF[7] = {0, 8390848LL, 4196224LL, 2098688LL,
                                   1049728LL, 525056LL, 262528LL};

    __shared__ __align__(16) float buf0[4512];   // 8 + 4474 + 8 margin
    __shared__ __align__(16) float buf1[2272];   // 8 + 2234 + 8 margin

    const int tile = blockIdx.x;   // 0..64
    const int row  = blockIdx.y;   // 0..63
    const int tid  = threadIdx.x;

    int lo[7], hi[7];
    lo[6] = tile << 6;
    hi[6] = min(lo[6] + 64, M[6]);
#pragma unroll
    for (int l = 5; l >= 0; --l) {
        lo[l] = max(2 * lo[l + 1] - 6, 0);
        hi[l] = min(2 * hi[l + 1], M[l]);
    }

    // Stage level-0 input slice into buf0 (lo[0] even, width even).
    {
        const int w0 = hi[0] - lo[0];
        const float2* xr = reinterpret_cast<const float2*>(x + (size_t)row * 262144 + lo[0]);
        float2* b2 = reinterpret_cast<float2*>(buf0) + 4;   // data at float index 8
        for (int t = tid; t < (w0 >> 1); t += THREADS) b2[t] = xr[t];
        if (tid < 16) buf0[tid < 8 ? tid : w0 + tid] = 0.0f;  // zero margins
    }
    __syncthreads();

    float* src = buf0;
    float* dst = buf1;
#pragma unroll
    for (int l = 1; l <= 6; ++l) {
        const int llo   = lo[l], lhi = hi[l];
        const int wl    = lhi - llo;
        const int shalf = lo[l - 1] >> 1;
        const int al    = tile << (12 - l);   // owned-D lower bound (al - llo <= 186)

        if (l < 6 && tid < 16) dst[tid < 8 ? tid : wl + tid] = 0.0f;

        // window for output i lives at float2 index (i + 1 - shalf)
        const float2* sp = reinterpret_cast<const float2*>(src) + (llo + tid + 1 - shalf);
        float* outD = out + DOFF[l] + (size_t)row * M[l];

        if (l < 6) {
            float* dA = dst + 8 - llo;
            for (int i0 = llo + tid; i0 < lhi; i0 += 2 * THREADS, sp += 2 * THREADS) {
                float A0, D0;
                TAPS(sp, A0, D0);
                dA[i0] = A0;
                if (i0 >= al) outD[i0] = D0;
                const int i1 = i0 + THREADS;
                if (i1 < lhi) {                 // second output: always owned (halo < 256)
                    float A1, D1;
                    TAPS(sp + THREADS, A1, D1);
                    dA[i1] = A1;
                    outD[i1] = D1;
                }
            }
        } else {
            float* outA = out + (size_t)row * M[6];
            for (int i0 = llo + tid; i0 < lhi; i0 += THREADS, sp += THREADS) {
                float A0, D0;
                TAPS(sp, A0, D0);
                outA[i0] = A0;                  // lo[6] == al: every output owned
                outD[i0] = D0;
            }
        }
        __syncthreads();
        float* t = src; src = dst; dst = t;
    }
}

extern "C" void kernel_launch(void* const* d_in, const int* in_sizes, int n_in,
                              void* d_out, int out_size)
{
    (void)in_sizes; (void)n_in; (void)out_size;
    dim3 grid(NTILES, 64);
    dwt6_kernel<<<grid, THREADS>>>((const float*)d_in[0], (float*)d_out);
}